// round 1
// baseline (speedup 1.0000x reference)
#include <cuda_runtime.h>
#include <math.h>

#define BATCH 4
#define C 64
#define HH 256
#define WW 256
#define NPIX (HH*WW)
#define NHEADS 8
#define HD 8
#define NCHUNK 64
#define CHUNK (NPIX/NCHUNK)   // 1024

// ---------------- scratch (static device globals; no allocations) ----------------
__device__ float g_Q[BATCH*C*NPIX];           // 64 MB
__device__ float g_K[BATCH*C*NPIX];           // 64 MB
__device__ float g_V[BATCH*C*NPIX];           // 64 MB
__device__ float g_part[BATCH*NHEADS*NCHUNK*80];
__device__ float g_attn[BATCH*NHEADS*HD*HD];
__device__ float g_weff[BATCH*C*C];

// ---------------- packed f32x2 helpers ----------------
__device__ __forceinline__ unsigned long long pack2(float lo, float hi) {
    unsigned long long r;
    asm("mov.b64 %0, {%1,%2};" : "=l"(r)
        : "r"(__float_as_uint(lo)), "r"(__float_as_uint(hi)));
    return r;
}
__device__ __forceinline__ void unpack2(unsigned long long p, float& lo, float& hi) {
    unsigned int a, b;
    asm("mov.b64 {%0,%1}, %2;" : "=r"(a), "=r"(b) : "l"(p));
    lo = __uint_as_float(a); hi = __uint_as_float(b);
}
#define FMA2(acc, a, b) \
    asm("fma.rn.f32x2 %0, %1, %2, %0;" : "+l"(acc) : "l"(a), "l"(b))

// ---------------- kernel 1-3: fused conv1x1 + depthwise 3x3 ----------------
// One 16x16 output tile per block; conv1x1 computed on the 18x18 halo into smem,
// then depthwise 3x3 reads smem and writes the Q/K/V scratch buffer.
// Weight pairs (co 2p, 2p+1) are prepacked as u64 so the inner loop is pure FFMA2
// with LDS.128 weight fetches (2 pairs per load).
__global__ void __launch_bounds__(256, 2) conv_fused(
    const float* __restrict__ in, const float* __restrict__ w1,
    const float* __restrict__ wdw, int dst)
{
    extern __shared__ unsigned char smem[];
    float* s_t = (float*)smem;                                          // [64][324]
    unsigned long long* s_wp = (unsigned long long*)(smem + C*324*4);   // [64 ci][32 pairs]
    float* s_dw = (float*)(smem + C*324*4 + C*32*8);                    // [64*9]

    const int tid = threadIdx.x;
    const int b = blockIdx.z;
    const int ty0 = blockIdx.y * 16, tx0 = blockIdx.x * 16;

    // stage weights
    for (int idx = tid; idx < C*32; idx += 256) {
        const int ci = idx >> 5, p = idx & 31;
        s_wp[idx] = pack2(w1[(2*p)*C + ci], w1[(2*p+1)*C + ci]);
    }
    for (int idx = tid; idx < C*9; idx += 256) s_dw[idx] = wdw[idx];
    __syncthreads();

    const float* inb = in + b * (C*NPIX);

    // conv1x1 over the halo tile
    for (int p = tid; p < 324; p += 256) {
        const int hy = p / 18, hx = p - hy*18;
        const int gy = ty0 + hy - 1, gx = tx0 + hx - 1;
        if (gy >= 0 && gy < HH && gx >= 0 && gx < WW) {
            const int pix = gy*WW + gx;
            unsigned long long acc[32];
            #pragma unroll
            for (int q = 0; q < 32; q++) acc[q] = 0ULL;
            #pragma unroll 4
            for (int ci = 0; ci < C; ci++) {
                const float v = __ldg(inb + ci*NPIX + pix);
                const unsigned long long vv = pack2(v, v);
                const ulonglong2* wr = (const ulonglong2*)(s_wp + ci*32);
                #pragma unroll
                for (int q = 0; q < 16; q++) {
                    const ulonglong2 wq = wr[q];
                    FMA2(acc[2*q],   vv, wq.x);
                    FMA2(acc[2*q+1], vv, wq.y);
                }
            }
            #pragma unroll
            for (int q = 0; q < 32; q++) {
                float lo, hi; unpack2(acc[q], lo, hi);
                s_t[(2*q)*324 + p]   = lo;
                s_t[(2*q+1)*324 + p] = hi;
            }
        } else {
            #pragma unroll
            for (int c = 0; c < C; c++) s_t[c*324 + p] = 0.f;   // zero padding
        }
    }
    __syncthreads();

    // depthwise 3x3 (pad=1 already handled by halo zeros)
    float* outb = (dst == 0 ? g_Q : dst == 1 ? g_K : g_V) + b * (C*NPIX);
    const int py = tid >> 4, px = tid & 15;
    const int opix = (ty0 + py)*WW + (tx0 + px);
    #pragma unroll 4
    for (int c = 0; c < C; c++) {
        const float* t = s_t + c*324 + py*18 + px;
        const float* w = s_dw + c*9;
        const float r = w[0]*t[0]  + w[1]*t[1]  + w[2]*t[2]
                      + w[3]*t[18] + w[4]*t[19] + w[5]*t[20]
                      + w[6]*t[36] + w[7]*t[37] + w[8]*t[38];
        outb[c*NPIX + opix] = r;
    }
}

// ---------------- kernel 4: partial q.k dots + sum-of-squares ----------------
// Block = (chunk, head, batch). Accumulates 8x8 S plus qsq[8]/ksq[8] over 1024
// pixels, deterministic shuffle+smem reduction, writes 80 partials per block.
__global__ void __launch_bounds__(256) attn_partial()
{
    const int chunk = blockIdx.x, h = blockIdx.y, b = blockIdx.z;
    const int tid = threadIdx.x;
    const float* qb = g_Q + (b*C + h*HD) * NPIX;
    const float* kb = g_K + (b*C + h*HD) * NPIX;

    float S[64], qs[8], ks[8];
    #pragma unroll
    for (int i = 0; i < 64; i++) S[i] = 0.f;
    #pragma unroll
    for (int i = 0; i < 8; i++) { qs[i] = 0.f; ks[i] = 0.f; }

    const int n0 = chunk * CHUNK;
    for (int it = 0; it < CHUNK/256; it++) {
        const int n = n0 + it*256 + tid;
        float qv[8], kv[8];
        #pragma unroll
        for (int j = 0; j < 8; j++) { qv[j] = qb[j*NPIX + n]; kv[j] = kb[j*NPIX + n]; }
        #pragma unroll
        for (int c2 = 0; c2 < 8; c2++) {
            qs[c2] += qv[c2]*qv[c2];
            ks[c2] += kv[c2]*kv[c2];
            #pragma unroll
            for (int d = 0; d < 8; d++) S[c2*8 + d] += qv[c2]*kv[d];
        }
    }

    __shared__ float s_red[80*8];
    const int lane = tid & 31, wrp = tid >> 5;
    #pragma unroll
    for (int i = 0; i < 80; i++) {
        float v = (i < 64) ? S[i] : (i < 72 ? qs[i-64] : ks[i-72]);
        #pragma unroll
        for (int o = 16; o > 0; o >>= 1) v += __shfl_xor_sync(0xffffffffu, v, o);
        if (lane == 0) s_red[i*8 + wrp] = v;
    }
    __syncthreads();
    if (tid < 80) {
        float v = 0.f;
        #pragma unroll
        for (int w = 0; w < 8; w++) v += s_red[tid*8 + w];
        g_part[((b*NHEADS + h)*NCHUNK + chunk)*80 + tid] = v;
    }
}

// ---------------- kernel 5a: reduce partials, scale by norms/temp, softmax ----
__global__ void __launch_bounds__(128) attn_finalize(const float* __restrict__ temp)
{
    const int b = blockIdx.x >> 3, h = blockIdx.x & 7;
    const int tid = threadIdx.x;
    __shared__ float red[80];
    __shared__ float nq[8], nk[8];

    if (tid < 80) {
        float v = 0.f;
        const float* p = g_part + (b*NHEADS + h)*NCHUNK*80 + tid;
        #pragma unroll 8
        for (int ch = 0; ch < NCHUNK; ch++) v += p[ch*80];
        red[tid] = v;
    }
    __syncthreads();
    if (tid < 8)       nq[tid]   = fmaxf(sqrtf(red[64 + tid]),   1e-12f);
    else if (tid < 16) nk[tid-8] = fmaxf(sqrtf(red[72 + tid-8]), 1e-12f);
    __syncthreads();

    if (tid < 64) {
        const int c2 = tid >> 3, d = tid & 7;
        const float logit = red[c2*8 + d] / (nq[c2]*nk[d]) * temp[h];
        float m = logit;
        #pragma unroll
        for (int o = 4; o > 0; o >>= 1) m = fmaxf(m, __shfl_xor_sync(0xffffffffu, m, o, 8));
        const float e = expf(logit - m);
        float s = e;
        #pragma unroll
        for (int o = 4; o > 0; o >>= 1) s += __shfl_xor_sync(0xffffffffu, s, o, 8);
        g_attn[(b*NHEADS + h)*64 + tid] = e / s;
    }
}

// ---------------- kernel 5b: W_eff[b] = proj_w @ blockdiag(attn[b]) ----------
__global__ void __launch_bounds__(256) compute_weff(const float* __restrict__ proj_w)
{
    const int b = blockIdx.x;
    __shared__ float s_attn[NHEADS*64];
    __shared__ float s_proj[C*C];
    const int tid = threadIdx.x;
    for (int i = tid; i < NHEADS*64; i += 256) s_attn[i] = g_attn[b*NHEADS*64 + i];
    for (int i = tid; i < C*C; i += 256)       s_proj[i] = proj_w[i];
    __syncthreads();
    for (int t = tid; t < C*C; t += 256) {
        const int co = t >> 6, cv = t & 63, hh = cv >> 3, d = cv & 7;
        float acc = 0.f;
        #pragma unroll
        for (int cp = 0; cp < 8; cp++)
            acc += s_proj[co*64 + hh*8 + cp] * s_attn[hh*64 + cp*8 + d];
        g_weff[b*C*C + t] = acc;
    }
}

// ---------------- kernel 6: out = W_eff[b] @ v (fused attn@v + proj conv) ----
__global__ void __launch_bounds__(256, 2) apply_out(float* __restrict__ out)
{
    __shared__ unsigned long long s_wp[C*32];   // [cv][co-pair] packed
    const int b = blockIdx.y;
    const int tid = threadIdx.x;
    const int n = blockIdx.x*256 + tid;
    const float* wb = g_weff + b*C*C;
    for (int idx = tid; idx < C*32; idx += 256) {
        const int cv = idx >> 5, p = idx & 31;
        s_wp[idx] = pack2(wb[(2*p)*C + cv], wb[(2*p+1)*C + cv]);
    }
    __syncthreads();

    const float* vb = g_V + b*(C*NPIX);
    unsigned long long acc[32];
    #pragma unroll
    for (int q = 0; q < 32; q++) acc[q] = 0ULL;
    #pragma unroll 4
    for (int cv = 0; cv < C; cv++) {
        const float v = vb[cv*NPIX + n];
        const unsigned long long vv = pack2(v, v);
        const ulonglong2* wr = (const ulonglong2*)(s_wp + cv*32);
        #pragma unroll
        for (int q = 0; q < 16; q++) {
            const ulonglong2 wq = wr[q];
            FMA2(acc[2*q],   vv, wq.x);
            FMA2(acc[2*q+1], vv, wq.y);
        }
    }
    float* ob = out + b*(C*NPIX);
    #pragma unroll
    for (int q = 0; q < 32; q++) {
        float lo, hi; unpack2(acc[q], lo, hi);
        ob[(2*q)*NPIX + n]   = lo;
        ob[(2*q+1)*NPIX + n] = hi;
    }
}

// ---------------- launcher ----------------
extern "C" void kernel_launch(void* const* d_in, const int* in_sizes, int n_in,
                              void* d_out, int out_size)
{
    const float* input1      = (const float*)d_in[0];
    const float* input2      = (const float*)d_in[1];
    const float* q_w         = (const float*)d_in[2];
    const float* q_dw_w      = (const float*)d_in[3];
    const float* kv_w        = (const float*)d_in[4];
    const float* kv_dw_w     = (const float*)d_in[5];
    const float* proj_w      = (const float*)d_in[6];
    const float* temperature = (const float*)d_in[7];
    float* out = (float*)d_out;

    const int SMEM1 = C*324*4 + C*32*8 + C*9*4;   // 101632 bytes
    cudaFuncSetAttribute(conv_fused, cudaFuncAttributeMaxDynamicSharedMemorySize, SMEM1);

    dim3 gconv(WW/16, HH/16, BATCH);
    conv_fused<<<gconv, 256, SMEM1>>>(input1, q_w, q_dw_w, 0);
    conv_fused<<<gconv, 256, SMEM1>>>(input2, kv_w,        kv_dw_w,        1);
    conv_fused<<<gconv, 256, SMEM1>>>(input2, kv_w + C*C,  kv_dw_w + C*9,  2);
    attn_partial<<<dim3(NCHUNK, NHEADS, BATCH), 256>>>();
    attn_finalize<<<BATCH*NHEADS, 128>>>(temperature);
    compute_weff<<<BATCH, 256>>>(proj_w);
    apply_out<<<dim3(NPIX/256, BATCH), 256>>>(out);
}